// round 12
// baseline (speedup 1.0000x reference)
#include <cuda_runtime.h>
#include <cuda_fp16.h>
#include <mma.h>
#include <math.h>
#include <stdint.h>

using namespace nvcuda;

#define NMAX 100000
#define EMAX 1600000

__device__ __half g_h1h[NMAX * 128];
__device__ __half g_x2h[NMAX * 128];
__device__ __half g_h2h[NMAX * 64];
__device__ float  g_as1[NMAX * 8];
__device__ float  g_ad1[NMAX * 8];
__device__ float  g_as2[NMAX];
__device__ float  g_ad2[NMAX];
__device__ int    g_cnt[NMAX];
__device__ int    g_cnt2[NMAX];
__device__ int    g_fillbase[NMAX];
__device__ int    g_srcs[EMAX];
__device__ int    g_bsum[512];
__device__ int    g_boff[512];

__device__ __forceinline__ float lrelu(float x) { return x > 0.f ? x : 0.2f * x; }
__device__ __forceinline__ float elu1(float x)  { return x > 0.f ? x : (__expf(x) - 1.f); }

// ---------------- CSR build ---------------------------------------------------
__global__ void hist_kernel(const int* __restrict__ ei, int e) {
    int i = blockIdx.x * blockDim.x + threadIdx.x;
    if (i < e) atomicAdd(&g_cnt[ei[e + i]], 1);
}

__global__ void scan1_kernel(int n) {
    __shared__ int wsum[32];
    int t = threadIdx.x;
    int lane = t & 31;
    int wid = t >> 5;
    int i = blockIdx.x * 1024 + t;
    int v = (i < n) ? g_cnt[i] : 0;
    int x = v;
    #pragma unroll
    for (int off = 1; off < 32; off <<= 1) {
        int u = __shfl_up_sync(0xffffffffu, x, off);
        if (lane >= off) x += u;
    }
    if (lane == 31) wsum[wid] = x;
    __syncthreads();
    if (wid == 0) {
        int s = wsum[lane];
        #pragma unroll
        for (int off = 1; off < 32; off <<= 1) {
            int u = __shfl_up_sync(0xffffffffu, s, off);
            if (lane >= off) s += u;
        }
        wsum[lane] = s;
    }
    __syncthreads();
    int incl = x + (wid ? wsum[wid - 1] : 0);
    if (i < n) g_fillbase[i] = incl - v;
    if (t == 1023) g_bsum[blockIdx.x] = incl;
}

__global__ void scan2_kernel(int nb) {
    __shared__ int wsum[32];
    int t = threadIdx.x;
    int lane = t & 31;
    int wid = t >> 5;
    int v = (t < nb) ? g_bsum[t] : 0;
    int x = v;
    #pragma unroll
    for (int off = 1; off < 32; off <<= 1) {
        int u = __shfl_up_sync(0xffffffffu, x, off);
        if (lane >= off) x += u;
    }
    if (lane == 31) wsum[wid] = x;
    __syncthreads();
    if (wid == 0) {
        int s = wsum[lane];
        #pragma unroll
        for (int off = 1; off < 32; off <<= 1) {
            int u = __shfl_up_sync(0xffffffffu, s, off);
            if (lane >= off) s += u;
        }
        wsum[lane] = s;
    }
    __syncthreads();
    int incl = x + (wid ? wsum[wid - 1] : 0);
    if (t < nb) g_boff[t] = incl - v;
}

__global__ void scatter_kernel(const int* __restrict__ ei, int e) {
    int i = blockIdx.x * blockDim.x + threadIdx.x;
    if (i < e) {
        int s = ei[i];
        int d = ei[e + i];
        int base = g_fillbase[d] + g_boff[d >> 10];
        int pos = base + atomicAdd(&g_cnt2[d], 1);
        g_srcs[pos] = s;
    }
}

// ---------------- GEMM1 (wmma) + att1 fold ------------------------------------
__global__ void gemm1_kernel(const float* __restrict__ A, const float* __restrict__ B,
                             const float* __restrict__ att_s, const float* __restrict__ att_d,
                             int M) {
    __shared__ __half sA[64 * 40];
    __shared__ __half sB[32 * 136];
    __shared__ float  sC[64 * 132];
    int tid = threadIdx.x;
    int wid = tid >> 5;
    int row0 = blockIdx.x * 64;
    int mr = (wid >> 1) * 16;
    int nc = (wid & 1) * 64;

    wmma::fragment<wmma::accumulator, 16, 16, 16, float> cf[4];
    #pragma unroll
    for (int j = 0; j < 4; j++) wmma::fill_fragment(cf[j], 0.f);

    int ar = tid >> 2;
    int ac = (tid & 3) * 8;
    int br = tid >> 3;
    int bc = (tid & 7) * 16;

    for (int k0 = 0; k0 < 256; k0 += 32) {
        int grow = row0 + ar;
        float4 v0;
        float4 v1;
        if (grow < M) {
            const float4* ap = (const float4*)(A + (size_t)grow * 256 + k0 + ac);
            v0 = ap[0];
            v1 = ap[1];
        } else {
            v0 = make_float4(0.f, 0.f, 0.f, 0.f);
            v1 = v0;
        }
        __half2* adst = (__half2*)&sA[ar * 40 + ac];
        adst[0] = __floats2half2_rn(v0.x, v0.y);
        adst[1] = __floats2half2_rn(v0.z, v0.w);
        adst[2] = __floats2half2_rn(v1.x, v1.y);
        adst[3] = __floats2half2_rn(v1.z, v1.w);

        const float4* bp = (const float4*)(B + (size_t)(k0 + br) * 128 + bc);
        float4 w0 = bp[0];
        float4 w1 = bp[1];
        float4 w2 = bp[2];
        float4 w3 = bp[3];
        __half2* bdst = (__half2*)&sB[br * 136 + bc];
        bdst[0] = __floats2half2_rn(w0.x, w0.y);
        bdst[1] = __floats2half2_rn(w0.z, w0.w);
        bdst[2] = __floats2half2_rn(w1.x, w1.y);
        bdst[3] = __floats2half2_rn(w1.z, w1.w);
        bdst[4] = __floats2half2_rn(w2.x, w2.y);
        bdst[5] = __floats2half2_rn(w2.z, w2.w);
        bdst[6] = __floats2half2_rn(w3.x, w3.y);
        bdst[7] = __floats2half2_rn(w3.z, w3.w);
        __syncthreads();

        #pragma unroll
        for (int kk = 0; kk < 32; kk += 16) {
            wmma::fragment<wmma::matrix_a, 16, 16, 16, __half, wmma::row_major> af;
            wmma::load_matrix_sync(af, &sA[mr * 40 + kk], 40);
            #pragma unroll
            for (int j = 0; j < 4; j++) {
                wmma::fragment<wmma::matrix_b, 16, 16, 16, __half, wmma::row_major> bf;
                wmma::load_matrix_sync(bf, &sB[kk * 136 + nc + j * 16], 136);
                wmma::mma_sync(cf[j], af, bf, cf[j]);
            }
        }
        __syncthreads();
    }

    #pragma unroll
    for (int j = 0; j < 4; j++) {
        wmma::store_matrix_sync(&sC[mr * 132 + nc + j * 16], cf[j], 132, wmma::mem_row_major);
    }
    __syncthreads();

    int erow = tid >> 2;
    int ec = tid & 3;
    int grow = row0 + erow;
    if (grow < M) {
        int col0 = ec * 32;
        float vals[32];
        #pragma unroll
        for (int j = 0; j < 32; j++) vals[j] = sC[erow * 132 + col0 + j];
        __half2 hv[16];
        #pragma unroll
        for (int j = 0; j < 16; j++) hv[j] = __floats2half2_rn(vals[2 * j], vals[2 * j + 1]);
        uint4* hdst = (uint4*)&g_h1h[(size_t)grow * 128 + col0];
        hdst[0] = *(uint4*)&hv[0];
        hdst[1] = *(uint4*)&hv[4];
        hdst[2] = *(uint4*)&hv[8];
        hdst[3] = *(uint4*)&hv[12];
        #pragma unroll
        for (int hh = 0; hh < 2; hh++) {
            int head = 2 * ec + hh;
            float ssum = 0.f;
            float dsum = 0.f;
            #pragma unroll
            for (int j = 0; j < 16; j++) {
                float vv = vals[hh * 16 + j];
                ssum += vv * __ldg(&att_s[head * 16 + j]);
                dsum += vv * __ldg(&att_d[head * 16 + j]);
            }
            g_as1[grow * 8 + head] = ssum;
            g_ad1[grow * 8 + head] = dsum;
        }
    }
}

// ---------------- layer-1 gather (two-phase, warp per node) -------------------
__global__ void gat1_kernel(const float* __restrict__ b1, int n) {
    int node = (blockIdx.x * blockDim.x + threadIdx.x) >> 5;
    int lid = threadIdx.x & 31;
    if (node >= n) return;
    int beg = g_fillbase[node] + g_boff[node >> 10];
    int deg = g_cnt2[node];
    int endd = beg + deg;

    int h = lid >> 2;
    int eo = lid >> 3;
    int hh = lid & 7;
    float adl = g_ad1[node * 8 + hh];
    float4 acc = make_float4(0.f, 0.f, 0.f, 0.f);
    float dpart = 0.f;

    for (int base = beg; base < endd; base += 32) {
        int cnt = endd - base;
        if (cnt > 32) cnt = 32;
        int ng = (cnt + 3) >> 2;
        int sidx = (base + lid < endd) ? __ldg(&g_srcs[base + lid]) : 0;
        // phase 1: weights for all groups (independent loads in flight)
        float wreg[8];
        #pragma unroll
        for (int gg = 0; gg < 8; gg++) {
            wreg[gg] = 0.f;
            if (gg < ng) {
                int ej = gg * 4 + eo;
                int sj = __shfl_sync(0xffffffffu, sidx, ej);
                if (ej < cnt) {
                    wreg[gg] = __expf(lrelu(__ldg(&g_as1[sj * 8 + hh]) + adl));
                }
                dpart += wreg[gg];
            }
        }
        // phase 2: pure accumulate
        #pragma unroll
        for (int gg = 0; gg < 8; gg++) {
            if (gg >= ng) break;
            #pragma unroll
            for (int q = 0; q < 4; q++) {
                int ej = gg * 4 + q;
                if (ej >= cnt) break;
                float wq = __shfl_sync(0xffffffffu, wreg[gg], q * 8 + h);
                int sq = __shfl_sync(0xffffffffu, sidx, ej);
                uint2 hvv = *(const uint2*)&g_h1h[(size_t)sq * 128 + lid * 4];
                float2 f0 = __half22float2(*(__half2*)&hvv.x);
                float2 f1 = __half22float2(*(__half2*)&hvv.y);
                acc.x += wq * f0.x;
                acc.y += wq * f0.y;
                acc.z += wq * f1.x;
                acc.w += wq * f1.y;
            }
        }
    }
    float dsum = dpart;
    dsum += __shfl_xor_sync(0xffffffffu, dsum, 8);
    dsum += __shfl_xor_sync(0xffffffffu, dsum, 16);
    float dh = __shfl_sync(0xffffffffu, dsum, h);
    float inv = 1.f / (dh + 1e-16f);
    float4 bb = *(const float4*)&b1[lid * 4];
    __half2 o0 = __floats2half2_rn(elu1(acc.x * inv + bb.x), elu1(acc.y * inv + bb.y));
    __half2 o1 = __floats2half2_rn(elu1(acc.z * inv + bb.z), elu1(acc.w * inv + bb.w));
    uint2 pk;
    pk.x = *(unsigned int*)&o0;
    pk.y = *(unsigned int*)&o1;
    *(uint2*)&g_x2h[(size_t)node * 128 + lid * 4] = pk;
    if (lid == 0) g_cnt[node] = 0;
}

// ---------------- GEMM2 (wmma) + att2 fold ------------------------------------
__global__ void gemm2_kernel(const float* __restrict__ B,
                             const float* __restrict__ att_s, const float* __restrict__ att_d,
                             int M) {
    __shared__ __half tA[64 * 40];
    __shared__ __half tB[32 * 72];
    __shared__ float  tC[64 * 68];
    int tid = threadIdx.x;
    int wid = tid >> 5;
    int row0 = blockIdx.x * 64;
    int mr = (wid >> 1) * 16;
    int nc = (wid & 1) * 32;

    wmma::fragment<wmma::accumulator, 16, 16, 16, float> cf[2];
    wmma::fill_fragment(cf[0], 0.f);
    wmma::fill_fragment(cf[1], 0.f);

    int ar = tid >> 2;
    int ac = (tid & 3) * 8;
    int br = tid >> 3;
    int bc = (tid & 7) * 8;

    for (int k0 = 0; k0 < 128; k0 += 32) {
        int grow = row0 + ar;
        uint4 av;
        if (grow < M) {
            av = *(const uint4*)&g_x2h[(size_t)grow * 128 + k0 + ac];
        } else {
            av = make_uint4(0u, 0u, 0u, 0u);
        }
        *(uint4*)&tA[ar * 40 + ac] = av;

        const float4* bp = (const float4*)(B + (size_t)(k0 + br) * 64 + bc);
        float4 w0 = bp[0];
        float4 w1 = bp[1];
        __half2* bdst = (__half2*)&tB[br * 72 + bc];
        bdst[0] = __floats2half2_rn(w0.x, w0.y);
        bdst[1] = __floats2half2_rn(w0.z, w0.w);
        bdst[2] = __floats2half2_rn(w1.x, w1.y);
        bdst[3] = __floats2half2_rn(w1.z, w1.w);
        __syncthreads();

        #pragma unroll
        for (int kk = 0; kk < 32; kk += 16) {
            wmma::fragment<wmma::matrix_a, 16, 16, 16, __half, wmma::row_major> af;
            wmma::load_matrix_sync(af, &tA[mr * 40 + kk], 40);
            #pragma unroll
            for (int j = 0; j < 2; j++) {
                wmma::fragment<wmma::matrix_b, 16, 16, 16, __half, wmma::row_major> bf;
                wmma::load_matrix_sync(bf, &tB[kk * 72 + nc + j * 16], 72);
                wmma::mma_sync(cf[j], af, bf, cf[j]);
            }
        }
        __syncthreads();
    }

    wmma::store_matrix_sync(&tC[mr * 68 + nc], cf[0], 68, wmma::mem_row_major);
    wmma::store_matrix_sync(&tC[mr * 68 + nc + 16], cf[1], 68, wmma::mem_row_major);
    __syncthreads();

    int erow = tid >> 2;
    int ec = tid & 3;
    int grow = row0 + erow;
    float ssum = 0.f;
    float dsum = 0.f;
    if (grow < M) {
        int col0 = ec * 16;
        float vals[16];
        #pragma unroll
        for (int j = 0; j < 16; j++) vals[j] = tC[erow * 68 + col0 + j];
        __half2 hv[8];
        #pragma unroll
        for (int j = 0; j < 8; j++) hv[j] = __floats2half2_rn(vals[2 * j], vals[2 * j + 1]);
        uint4* hdst = (uint4*)&g_h2h[(size_t)grow * 64 + col0];
        hdst[0] = *(uint4*)&hv[0];
        hdst[1] = *(uint4*)&hv[4];
        #pragma unroll
        for (int j = 0; j < 16; j++) {
            float vv = vals[j];
            ssum += vv * __ldg(&att_s[col0 + j]);
            dsum += vv * __ldg(&att_d[col0 + j]);
        }
    }
    ssum += __shfl_xor_sync(0xffffffffu, ssum, 1);
    ssum += __shfl_xor_sync(0xffffffffu, ssum, 2);
    dsum += __shfl_xor_sync(0xffffffffu, dsum, 1);
    dsum += __shfl_xor_sync(0xffffffffu, dsum, 2);
    if (ec == 0 && grow < M) {
        g_as2[grow] = ssum;
        g_ad2[grow] = dsum;
    }
}

// ---------------- layer-2 gather (full-width weights) + log_softmax -----------
__global__ void gat2_kernel(const float* __restrict__ b2, float* __restrict__ out, int n) {
    int node = (blockIdx.x * blockDim.x + threadIdx.x) >> 5;
    int lid = threadIdx.x & 31;
    if (node >= n) return;
    int beg = g_fillbase[node] + g_boff[node >> 10];
    int deg = g_cnt2[node];
    int endd = beg + deg;
    float adn = g_ad2[node];

    float acc0 = 0.f;
    float acc1 = 0.f;
    float dpart = 0.f;
    for (int base = beg; base < endd; base += 32) {
        int cnt = endd - base;
        if (cnt > 32) cnt = 32;
        int sidx = 0;
        float w = 0.f;
        if (base + lid < endd) {
            sidx = __ldg(&g_srcs[base + lid]);
            w = __expf(lrelu(__ldg(&g_as2[sidx]) + adn));
        }
        dpart += w;
        #pragma unroll 4
        for (int q = 0; q < 32; q++) {
            if (q >= cnt) break;
            float wq = __shfl_sync(0xffffffffu, w, q);
            int sq = __shfl_sync(0xffffffffu, sidx, q);
            __half2 hvv = *(const __half2*)&g_h2h[(size_t)sq * 64 + lid * 2];
            float2 v = __half22float2(hvv);
            acc0 += wq * v.x;
            acc1 += wq * v.y;
        }
    }
    float dt = dpart;
    #pragma unroll
    for (int off = 16; off; off >>= 1) dt += __shfl_xor_sync(0xffffffffu, dt, off);
    float inv = 1.f / (dt + 1e-16f);
    float o0 = acc0 * inv + __ldg(&b2[lid * 2]);
    float o1 = acc1 * inv + __ldg(&b2[lid * 2 + 1]);

    float rm = fmaxf(o0, o1);
    #pragma unroll
    for (int off = 16; off; off >>= 1) rm = fmaxf(rm, __shfl_xor_sync(0xffffffffu, rm, off));
    float se = __expf(o0 - rm) + __expf(o1 - rm);
    #pragma unroll
    for (int off = 16; off; off >>= 1) se += __shfl_xor_sync(0xffffffffu, se, off);
    float lse = rm + __logf(se);

    float2 res;
    res.x = o0 - lse;
    res.y = o1 - lse;
    *(float2*)&out[(size_t)node * 64 + lid * 2] = res;
    if (lid == 0) g_cnt2[node] = 0;
}

// ---------------- launch ------------------------------------------------------
extern "C" void kernel_launch(void* const* d_in, const int* in_sizes, int n_in,
                              void* d_out, int out_size) {
    const float* x      = (const float*)d_in[0];
    const int*   ei     = (const int*)d_in[1];
    const float* W1     = (const float*)d_in[2];
    const float* att1_s = (const float*)d_in[3];
    const float* att1_d = (const float*)d_in[4];
    const float* b1     = (const float*)d_in[5];
    const float* W2     = (const float*)d_in[6];
    const float* att2_s = (const float*)d_in[7];
    const float* att2_d = (const float*)d_in[8];
    const float* b2     = (const float*)d_in[9];
    float* out = (float*)d_out;

    int n = in_sizes[0] / 256;
    int e = in_sizes[1] / 2;
    int nb = (n + 1023) / 1024;

    static cudaStream_t s2 = nullptr;
    static cudaEvent_t evFork = nullptr;
    static cudaEvent_t evJoin = nullptr;
    if (!s2) {
        cudaStreamCreateWithFlags(&s2, cudaStreamNonBlocking);
        cudaEventCreateWithFlags(&evFork, cudaEventDisableTiming);
        cudaEventCreateWithFlags(&evJoin, cudaEventDisableTiming);
    }

    cudaEventRecord(evFork, 0);
    cudaStreamWaitEvent(s2, evFork, 0);
    gemm1_kernel<<<(n + 63) / 64, 256, 0, s2>>>(x, W1, att1_s, att1_d, n);
    cudaEventRecord(evJoin, s2);

    hist_kernel<<<(e + 255) / 256, 256>>>(ei, e);
    scan1_kernel<<<nb, 1024>>>(n);
    scan2_kernel<<<1, 512>>>(nb);
    scatter_kernel<<<(e + 255) / 256, 256>>>(ei, e);

    cudaStreamWaitEvent(0, evJoin, 0);
    gat1_kernel<<<(n + 7) / 8, 256>>>(b1, n);
    gemm2_kernel<<<(n + 63) / 64, 256>>>(W2, att2_s, att2_d, n);
    gat2_kernel<<<(n + 7) / 8, 256>>>(b2, out, n);
}

// round 14
// speedup vs baseline: 1.5666x; 1.5666x over previous
#include <cuda_runtime.h>
#include <cuda_fp16.h>
#include <mma.h>
#include <math.h>
#include <stdint.h>

using namespace nvcuda;

#define NMAX 100000
#define EMAX 1600000

__device__ __half g_h1h[NMAX * 128];
__device__ __half g_x2h[NMAX * 128];
__device__ __half g_h2h[NMAX * 64];
__device__ float  g_as1[NMAX * 8];
__device__ float  g_ad1[NMAX * 8];
__device__ float  g_as2[NMAX];
__device__ float  g_ad2[NMAX];
__device__ int    g_cnt[NMAX];
__device__ int    g_cnt2[NMAX];
__device__ int    g_fillbase[NMAX];
__device__ int    g_srcs[EMAX];
__device__ int    g_bsum[512];
__device__ int    g_boff[512];

__device__ __forceinline__ float lrelu(float x) { return x > 0.f ? x : 0.2f * x; }
__device__ __forceinline__ float elu1(float x)  { return x > 0.f ? x : (__expf(x) - 1.f); }

// ---------------- CSR build ---------------------------------------------------
__global__ void hist_kernel(const int* __restrict__ ei, int e) {
    int i = blockIdx.x * blockDim.x + threadIdx.x;
    if (i < e) atomicAdd(&g_cnt[ei[e + i]], 1);
}

__global__ void scan1_kernel(int n) {
    __shared__ int wsum[32];
    int t = threadIdx.x;
    int lane = t & 31;
    int wid = t >> 5;
    int i = blockIdx.x * 1024 + t;
    int v = (i < n) ? g_cnt[i] : 0;
    int x = v;
    #pragma unroll
    for (int off = 1; off < 32; off <<= 1) {
        int u = __shfl_up_sync(0xffffffffu, x, off);
        if (lane >= off) x += u;
    }
    if (lane == 31) wsum[wid] = x;
    __syncthreads();
    if (wid == 0) {
        int s = wsum[lane];
        #pragma unroll
        for (int off = 1; off < 32; off <<= 1) {
            int u = __shfl_up_sync(0xffffffffu, s, off);
            if (lane >= off) s += u;
        }
        wsum[lane] = s;
    }
    __syncthreads();
    int incl = x + (wid ? wsum[wid - 1] : 0);
    if (i < n) g_fillbase[i] = incl - v;
    if (t == 1023) g_bsum[blockIdx.x] = incl;
}

__global__ void scan2_kernel(int nb) {
    __shared__ int wsum[32];
    int t = threadIdx.x;
    int lane = t & 31;
    int wid = t >> 5;
    int v = (t < nb) ? g_bsum[t] : 0;
    int x = v;
    #pragma unroll
    for (int off = 1; off < 32; off <<= 1) {
        int u = __shfl_up_sync(0xffffffffu, x, off);
        if (lane >= off) x += u;
    }
    if (lane == 31) wsum[wid] = x;
    __syncthreads();
    if (wid == 0) {
        int s = wsum[lane];
        #pragma unroll
        for (int off = 1; off < 32; off <<= 1) {
            int u = __shfl_up_sync(0xffffffffu, s, off);
            if (lane >= off) s += u;
        }
        wsum[lane] = s;
    }
    __syncthreads();
    int incl = x + (wid ? wsum[wid - 1] : 0);
    if (t < nb) g_boff[t] = incl - v;
}

__global__ void scatter_kernel(const int* __restrict__ ei, int e) {
    int i = blockIdx.x * blockDim.x + threadIdx.x;
    if (i < e) {
        int s = ei[i];
        int d = ei[e + i];
        int base = g_fillbase[d] + g_boff[d >> 10];
        int pos = base + atomicAdd(&g_cnt2[d], 1);
        g_srcs[pos] = s;
    }
}

// ---------------- GEMM1 (wmma) + att1 fold ------------------------------------
__global__ void gemm1_kernel(const float* __restrict__ A, const float* __restrict__ B,
                             const float* __restrict__ att_s, const float* __restrict__ att_d,
                             int M) {
    __shared__ __half sA[64 * 40];
    __shared__ __half sB[32 * 136];
    __shared__ float  sC[64 * 132];
    int tid = threadIdx.x;
    int wid = tid >> 5;
    int row0 = blockIdx.x * 64;
    int mr = (wid >> 1) * 16;
    int nc = (wid & 1) * 64;

    wmma::fragment<wmma::accumulator, 16, 16, 16, float> cf[4];
    #pragma unroll
    for (int j = 0; j < 4; j++) wmma::fill_fragment(cf[j], 0.f);

    int ar = tid >> 2;
    int ac = (tid & 3) * 8;
    int br = tid >> 3;
    int bc = (tid & 7) * 16;

    for (int k0 = 0; k0 < 256; k0 += 32) {
        int grow = row0 + ar;
        float4 v0;
        float4 v1;
        if (grow < M) {
            const float4* ap = (const float4*)(A + (size_t)grow * 256 + k0 + ac);
            v0 = ap[0];
            v1 = ap[1];
        } else {
            v0 = make_float4(0.f, 0.f, 0.f, 0.f);
            v1 = v0;
        }
        __half2* adst = (__half2*)&sA[ar * 40 + ac];
        adst[0] = __floats2half2_rn(v0.x, v0.y);
        adst[1] = __floats2half2_rn(v0.z, v0.w);
        adst[2] = __floats2half2_rn(v1.x, v1.y);
        adst[3] = __floats2half2_rn(v1.z, v1.w);

        const float4* bp = (const float4*)(B + (size_t)(k0 + br) * 128 + bc);
        float4 w0 = bp[0];
        float4 w1 = bp[1];
        float4 w2 = bp[2];
        float4 w3 = bp[3];
        __half2* bdst = (__half2*)&sB[br * 136 + bc];
        bdst[0] = __floats2half2_rn(w0.x, w0.y);
        bdst[1] = __floats2half2_rn(w0.z, w0.w);
        bdst[2] = __floats2half2_rn(w1.x, w1.y);
        bdst[3] = __floats2half2_rn(w1.z, w1.w);
        bdst[4] = __floats2half2_rn(w2.x, w2.y);
        bdst[5] = __floats2half2_rn(w2.z, w2.w);
        bdst[6] = __floats2half2_rn(w3.x, w3.y);
        bdst[7] = __floats2half2_rn(w3.z, w3.w);
        __syncthreads();

        #pragma unroll
        for (int kk = 0; kk < 32; kk += 16) {
            wmma::fragment<wmma::matrix_a, 16, 16, 16, __half, wmma::row_major> af;
            wmma::load_matrix_sync(af, &sA[mr * 40 + kk], 40);
            #pragma unroll
            for (int j = 0; j < 4; j++) {
                wmma::fragment<wmma::matrix_b, 16, 16, 16, __half, wmma::row_major> bf;
                wmma::load_matrix_sync(bf, &sB[kk * 136 + nc + j * 16], 136);
                wmma::mma_sync(cf[j], af, bf, cf[j]);
            }
        }
        __syncthreads();
    }

    #pragma unroll
    for (int j = 0; j < 4; j++) {
        wmma::store_matrix_sync(&sC[mr * 132 + nc + j * 16], cf[j], 132, wmma::mem_row_major);
    }
    __syncthreads();

    int erow = tid >> 2;
    int ec = tid & 3;
    int grow = row0 + erow;
    if (grow < M) {
        int col0 = ec * 32;
        float vals[32];
        #pragma unroll
        for (int j = 0; j < 32; j++) vals[j] = sC[erow * 132 + col0 + j];
        __half2 hv[16];
        #pragma unroll
        for (int j = 0; j < 16; j++) hv[j] = __floats2half2_rn(vals[2 * j], vals[2 * j + 1]);
        uint4* hdst = (uint4*)&g_h1h[(size_t)grow * 128 + col0];
        hdst[0] = *(uint4*)&hv[0];
        hdst[1] = *(uint4*)&hv[4];
        hdst[2] = *(uint4*)&hv[8];
        hdst[3] = *(uint4*)&hv[12];
        #pragma unroll
        for (int hh = 0; hh < 2; hh++) {
            int head = 2 * ec + hh;
            float ssum = 0.f;
            float dsum = 0.f;
            #pragma unroll
            for (int j = 0; j < 16; j++) {
                float vv = vals[hh * 16 + j];
                ssum += vv * __ldg(&att_s[head * 16 + j]);
                dsum += vv * __ldg(&att_d[head * 16 + j]);
            }
            g_as1[grow * 8 + head] = ssum;
            g_ad1[grow * 8 + head] = dsum;
        }
    }
}

// ---------------- layer-1 gather (R10 structure + 2-reg weight pipeline) ------
__global__ void gat1_kernel(const float* __restrict__ b1, int n) {
    int node = (blockIdx.x * blockDim.x + threadIdx.x) >> 5;
    int lid = threadIdx.x & 31;
    if (node >= n) return;
    int beg = g_fillbase[node] + g_boff[node >> 10];
    int end = beg + g_cnt2[node];

    int h = lid >> 2;
    int eo = lid >> 3;
    int hh = lid & 7;
    float adl = g_ad1[node * 8 + hh];
    float4 acc = make_float4(0.f, 0.f, 0.f, 0.f);
    float dpart = 0.f;

    for (int base = beg; base < end; base += 32) {
        int cnt = end - base;
        if (cnt > 32) cnt = 32;
        int sidx = (base + lid < end) ? __ldg(&g_srcs[base + lid]) : 0;
        // prologue: weight for group 0 (lanes hold edge g+eo, head hh)
        float wcur = 0.f;
        {
            int sj0 = __shfl_sync(0xffffffffu, sidx, eo);
            if (eo < cnt) wcur = __expf(lrelu(__ldg(&g_as1[sj0 * 8 + hh]) + adl));
        }
        for (int g = 0; g < cnt; g += 4) {
            // issue next group's weight chain before this group's feature loads
            float wnext = 0.f;
            int gn = g + 4;
            if (gn < cnt) {
                int sjn = __shfl_sync(0xffffffffu, sidx, gn + eo);
                if (gn + eo < cnt) wnext = __expf(lrelu(__ldg(&g_as1[sjn * 8 + hh]) + adl));
            }
            dpart += wcur;
            #pragma unroll
            for (int q = 0; q < 4; q++) {
                float wq = __shfl_sync(0xffffffffu, wcur, q * 8 + h);
                int sq = __shfl_sync(0xffffffffu, sidx, g + q);
                uint2 hvv = *(const uint2*)&g_h1h[(size_t)sq * 128 + lid * 4];
                float2 f0 = __half22float2(*(__half2*)&hvv.x);
                float2 f1 = __half22float2(*(__half2*)&hvv.y);
                acc.x += wq * f0.x;
                acc.y += wq * f0.y;
                acc.z += wq * f1.x;
                acc.w += wq * f1.y;
            }
            wcur = wnext;
        }
    }
    float dsum = dpart;
    dsum += __shfl_xor_sync(0xffffffffu, dsum, 8);
    dsum += __shfl_xor_sync(0xffffffffu, dsum, 16);
    float dh = __shfl_sync(0xffffffffu, dsum, h);
    float inv = 1.f / (dh + 1e-16f);
    float4 bb = *(const float4*)&b1[lid * 4];
    __half2 o0 = __floats2half2_rn(elu1(acc.x * inv + bb.x), elu1(acc.y * inv + bb.y));
    __half2 o1 = __floats2half2_rn(elu1(acc.z * inv + bb.z), elu1(acc.w * inv + bb.w));
    uint2 pk;
    pk.x = *(unsigned int*)&o0;
    pk.y = *(unsigned int*)&o1;
    *(uint2*)&g_x2h[(size_t)node * 128 + lid * 4] = pk;
    if (lid == 0) g_cnt[node] = 0;
}

// ---------------- GEMM2 (wmma) + att2 fold ------------------------------------
__global__ void gemm2_kernel(const float* __restrict__ B,
                             const float* __restrict__ att_s, const float* __restrict__ att_d,
                             int M) {
    __shared__ __half tA[64 * 40];
    __shared__ __half tB[32 * 72];
    __shared__ float  tC[64 * 68];
    int tid = threadIdx.x;
    int wid = tid >> 5;
    int row0 = blockIdx.x * 64;
    int mr = (wid >> 1) * 16;
    int nc = (wid & 1) * 32;

    wmma::fragment<wmma::accumulator, 16, 16, 16, float> cf[2];
    wmma::fill_fragment(cf[0], 0.f);
    wmma::fill_fragment(cf[1], 0.f);

    int ar = tid >> 2;
    int ac = (tid & 3) * 8;
    int br = tid >> 3;
    int bc = (tid & 7) * 8;

    for (int k0 = 0; k0 < 128; k0 += 32) {
        int grow = row0 + ar;
        uint4 av;
        if (grow < M) {
            av = *(const uint4*)&g_x2h[(size_t)grow * 128 + k0 + ac];
        } else {
            av = make_uint4(0u, 0u, 0u, 0u);
        }
        *(uint4*)&tA[ar * 40 + ac] = av;

        const float4* bp = (const float4*)(B + (size_t)(k0 + br) * 64 + bc);
        float4 w0 = bp[0];
        float4 w1 = bp[1];
        __half2* bdst = (__half2*)&tB[br * 72 + bc];
        bdst[0] = __floats2half2_rn(w0.x, w0.y);
        bdst[1] = __floats2half2_rn(w0.z, w0.w);
        bdst[2] = __floats2half2_rn(w1.x, w1.y);
        bdst[3] = __floats2half2_rn(w1.z, w1.w);
        __syncthreads();

        #pragma unroll
        for (int kk = 0; kk < 32; kk += 16) {
            wmma::fragment<wmma::matrix_a, 16, 16, 16, __half, wmma::row_major> af;
            wmma::load_matrix_sync(af, &tA[mr * 40 + kk], 40);
            #pragma unroll
            for (int j = 0; j < 2; j++) {
                wmma::fragment<wmma::matrix_b, 16, 16, 16, __half, wmma::row_major> bf;
                wmma::load_matrix_sync(bf, &tB[kk * 72 + nc + j * 16], 72);
                wmma::mma_sync(cf[j], af, bf, cf[j]);
            }
        }
        __syncthreads();
    }

    wmma::store_matrix_sync(&tC[mr * 68 + nc], cf[0], 68, wmma::mem_row_major);
    wmma::store_matrix_sync(&tC[mr * 68 + nc + 16], cf[1], 68, wmma::mem_row_major);
    __syncthreads();

    int erow = tid >> 2;
    int ec = tid & 3;
    int grow = row0 + erow;
    float ssum = 0.f;
    float dsum = 0.f;
    if (grow < M) {
        int col0 = ec * 16;
        float vals[16];
        #pragma unroll
        for (int j = 0; j < 16; j++) vals[j] = tC[erow * 68 + col0 + j];
        __half2 hv[8];
        #pragma unroll
        for (int j = 0; j < 8; j++) hv[j] = __floats2half2_rn(vals[2 * j], vals[2 * j + 1]);
        uint4* hdst = (uint4*)&g_h2h[(size_t)grow * 64 + col0];
        hdst[0] = *(uint4*)&hv[0];
        hdst[1] = *(uint4*)&hv[4];
        #pragma unroll
        for (int j = 0; j < 16; j++) {
            float vv = vals[j];
            ssum += vv * __ldg(&att_s[col0 + j]);
            dsum += vv * __ldg(&att_d[col0 + j]);
        }
    }
    ssum += __shfl_xor_sync(0xffffffffu, ssum, 1);
    ssum += __shfl_xor_sync(0xffffffffu, ssum, 2);
    dsum += __shfl_xor_sync(0xffffffffu, dsum, 1);
    dsum += __shfl_xor_sync(0xffffffffu, dsum, 2);
    if (ec == 0 && grow < M) {
        g_as2[grow] = ssum;
        g_ad2[grow] = dsum;
    }
}

// ---------------- layer-2 gather (R10 structure) + log_softmax ----------------
__global__ void gat2_kernel(const float* __restrict__ b2, float* __restrict__ out, int n) {
    int node = (blockIdx.x * blockDim.x + threadIdx.x) >> 5;
    int lid = threadIdx.x & 31;
    if (node >= n) return;
    int beg = g_fillbase[node] + g_boff[node >> 10];
    int end = beg + g_cnt2[node];
    float adn = g_ad2[node];

    float acc0 = 0.f;
    float acc1 = 0.f;
    float dpart = 0.f;
    for (int base = beg; base < end; base += 32) {
        int cnt = end - base;
        if (cnt > 32) cnt = 32;
        int sidx = (base + lid < end) ? __ldg(&g_srcs[base + lid]) : 0;
        for (int g = 0; g < cnt; g += 4) {
            int widx = g + (lid & 3);
            if (widx > 31) widx = 31;
            int sj = __shfl_sync(0xffffffffu, sidx, widx);
            float w = 0.f;
            if (lid < 4 && g + lid < cnt) w = __expf(lrelu(__ldg(&g_as2[sj]) + adn));
            dpart += w;
            #pragma unroll
            for (int q = 0; q < 4; q++) {
                float wq = __shfl_sync(0xffffffffu, w, q);
                int sq = __shfl_sync(0xffffffffu, sidx, g + q);
                __half2 hvv = *(const __half2*)&g_h2h[(size_t)sq * 64 + lid * 2];
                float2 v = __half22float2(hvv);
                acc0 += wq * v.x;
                acc1 += wq * v.y;
            }
        }
    }
    float dsum = dpart;
    dsum += __shfl_xor_sync(0xffffffffu, dsum, 1);
    dsum += __shfl_xor_sync(0xffffffffu, dsum, 2);
    float dt = __shfl_sync(0xffffffffu, dsum, 0);
    float inv = 1.f / (dt + 1e-16f);
    float o0 = acc0 * inv + __ldg(&b2[lid * 2]);
    float o1 = acc1 * inv + __ldg(&b2[lid * 2 + 1]);

    float rm = fmaxf(o0, o1);
    #pragma unroll
    for (int off = 16; off; off >>= 1) rm = fmaxf(rm, __shfl_xor_sync(0xffffffffu, rm, off));
    float se = __expf(o0 - rm) + __expf(o1 - rm);
    #pragma unroll
    for (int off = 16; off; off >>= 1) se += __shfl_xor_sync(0xffffffffu, se, off);
    float lse = rm + __logf(se);

    float2 res;
    res.x = o0 - lse;
    res.y = o1 - lse;
    *(float2*)&out[(size_t)node * 64 + lid * 2] = res;
    if (lid == 0) g_cnt2[node] = 0;
}

// ---------------- launch ------------------------------------------------------
extern "C" void kernel_launch(void* const* d_in, const int* in_sizes, int n_in,
                              void* d_out, int out_size) {
    const float* x      = (const float*)d_in[0];
    const int*   ei     = (const int*)d_in[1];
    const float* W1     = (const float*)d_in[2];
    const float* att1_s = (const float*)d_in[3];
    const float* att1_d = (const float*)d_in[4];
    const float* b1     = (const float*)d_in[5];
    const float* W2     = (const float*)d_in[6];
    const float* att2_s = (const float*)d_in[7];
    const float* att2_d = (const float*)d_in[8];
    const float* b2     = (const float*)d_in[9];
    float* out = (float*)d_out;

    int n = in_sizes[0] / 256;
    int e = in_sizes[1] / 2;
    int nb = (n + 1023) / 1024;

    static cudaStream_t s2 = nullptr;
    static cudaEvent_t evFork = nullptr;
    static cudaEvent_t evJoin = nullptr;
    if (!s2) {
        cudaStreamCreateWithFlags(&s2, cudaStreamNonBlocking);
        cudaEventCreateWithFlags(&evFork, cudaEventDisableTiming);
        cudaEventCreateWithFlags(&evJoin, cudaEventDisableTiming);
    }

    cudaEventRecord(evFork, 0);
    cudaStreamWaitEvent(s2, evFork, 0);
    gemm1_kernel<<<(n + 63) / 64, 256, 0, s2>>>(x, W1, att1_s, att1_d, n);
    cudaEventRecord(evJoin, s2);

    hist_kernel<<<(e + 255) / 256, 256>>>(ei, e);
    scan1_kernel<<<nb, 1024>>>(n);
    scan2_kernel<<<1, 512>>>(nb);
    scatter_kernel<<<(e + 255) / 256, 256>>>(ei, e);

    cudaStreamWaitEvent(0, evJoin, 0);
    gat1_kernel<<<(n + 7) / 8, 256>>>(b1, n);
    gemm2_kernel<<<(n + 63) / 64, 256>>>(W2, att2_s, att2_d, n);
    gat2_kernel<<<(n + 7) / 8, 256>>>(b2, out, n);
}